// round 16
// baseline (speedup 1.0000x reference)
#include <cuda_runtime.h>
#include <cuda_fp16.h>
#include <math.h>
#include <stdint.h>

#define T    2048
#define H    2048
#define NH   16
#define NKV  4
#define HD   128
#define E    8
#define I_DIM 4096
#define QKVW ((NH + 2*NKV) * HD)   /* 3072 */
#define EPSN 1e-5f
#define THETA_F 500000.0f
#define ATTN_SCALE 0.08838834764831845f

/* ===================== scratch (device globals) ===================== */
__device__ float g_res [T*H];
__device__ float g_qkv [T*QKVW];
__device__ int   g_topidx[T];
__device__ int   g_perm[T];
__device__ int   g_cnt[E];
__device__ int   g_off[E];
__device__ int   g_sync;
/* fp16 buffers */
__device__ uint4 g_act1[(size_t)T*I_DIM/8];
__device__ uint4 g_act2[(size_t)T*I_DIM/8];
__device__ uint4 g_ghs[(size_t)T*I_DIM/8];
__device__ uint4 g_uhs[(size_t)T*I_DIM/8];
__device__ uint4 g_ghr[(size_t)T*I_DIM/8];
__device__ uint4 g_uhr[(size_t)T*I_DIM/8];
__device__ uint4 g_qh[(size_t)T*NH*HD/8];
__device__ uint4 g_kh[(size_t)NKV*T*HD/8];
__device__ uint4 g_vh[(size_t)NKV*T*HD/8];

/* ===================== small PTX wrappers ===================== */
__device__ __forceinline__ uint32_t smem_u32(const void* p) {
    uint32_t a;
    asm("{ .reg .u64 t; cvta.to.shared.u64 t, %1; cvt.u32.u64 %0, t; }" : "=r"(a) : "l"(p));
    return a;
}
__device__ __forceinline__ void ldm4(uint32_t* r, uint32_t addr) {
    asm volatile("ldmatrix.sync.aligned.m8n8.x4.shared.b16 {%0,%1,%2,%3}, [%4];"
        : "=r"(r[0]), "=r"(r[1]), "=r"(r[2]), "=r"(r[3]) : "r"(addr));
}
__device__ __forceinline__ void ldm4t(uint32_t* r, uint32_t addr) {
    asm volatile("ldmatrix.sync.aligned.m8n8.x4.trans.shared.b16 {%0,%1,%2,%3}, [%4];"
        : "=r"(r[0]), "=r"(r[1]), "=r"(r[2]), "=r"(r[3]) : "r"(addr));
}
__device__ __forceinline__ void mma_f16(float* c, const uint32_t* a, const uint32_t* b) {
    asm volatile(
        "mma.sync.aligned.m16n8k16.row.col.f32.f16.f16.f32 "
        "{%0,%1,%2,%3}, {%4,%5,%6,%7}, {%8,%9}, {%0,%1,%2,%3};"
        : "+f"(c[0]), "+f"(c[1]), "+f"(c[2]), "+f"(c[3])
        : "r"(a[0]), "r"(a[1]), "r"(a[2]), "r"(a[3]), "r"(b[0]), "r"(b[1]));
}
#define CP16(dst, src, sz) asm volatile("cp.async.cg.shared.global [%0], [%1], 16, %2;" :: "r"(dst), "l"(src), "r"(sz) : "memory")
#define STS128(addr, v) asm volatile("st.shared.v4.b32 [%0], {%1,%2,%3,%4};" :: "r"(addr), "r"((v).x), "r"((v).y), "r"((v).z), "r"((v).w) : "memory")

__device__ __forceinline__ uint4 pack8h(float4 a, float4 b) {
    __half2 h0 = __floats2half2_rn(a.x, a.y);
    __half2 h1 = __floats2half2_rn(a.z, a.w);
    __half2 h2 = __floats2half2_rn(b.x, b.y);
    __half2 h3 = __floats2half2_rn(b.z, b.w);
    uint4 r;
    r.x = *(uint32_t*)&h0; r.y = *(uint32_t*)&h1;
    r.z = *(uint32_t*)&h2; r.w = *(uint32_t*)&h3;
    return r;
}

/* ===================== add + rmsnorm ===================== */
__global__ void addnorm_kernel(const float* __restrict__ a, const float* __restrict__ b,
                               const float* __restrict__ w, float* __restrict__ res,
                               float* __restrict__ xout, __half* __restrict__ xh)
{
    int t = blockIdx.x;
    int tid = threadIdx.x;
    const int PER = H / 256;
    size_t base = (size_t)t * H;
    float v[PER];
    float ss = 0.f;
#pragma unroll
    for (int u = 0; u < PER; u++) {
        int c = tid + u * 256;
        float val = a[base + c];
        if (b) val += b[base + c];
        v[u] = val;
        if (res) res[base + c] = val;
        ss += val * val;
    }
    __shared__ float red[256];
    red[tid] = ss;
    __syncthreads();
    for (int s = 128; s > 0; s >>= 1) {
        if (tid < s) red[tid] += red[tid + s];
        __syncthreads();
    }
    float scale = rsqrtf(red[0] / (float)H + EPSN);
#pragma unroll
    for (int u = 0; u < PER; u++) {
        int c = tid + u * 256;
        float o = v[u] * scale * w[c];
        if (xout) xout[base + c] = o;
        xh[base + c] = __float2half(o);
    }
}

/* ===================== fused rmsnorm(step6) + router + last-block hist ===================== */
__global__ void addnorm_router_kernel(const float* __restrict__ a,
                                      const float* __restrict__ w,
                                      const float* __restrict__ rw,
                                      int* __restrict__ topidx,
                                      __half* __restrict__ xh,
                                      __half* __restrict__ xwh)
{
    int t = blockIdx.x;
    int tid = threadIdx.x;
    const int PER = H / 256;
    size_t base = (size_t)t * H;
    float v[PER];
    float ss = 0.f;
#pragma unroll
    for (int u = 0; u < PER; u++) {
        int c = tid + u * 256;
        float val = a[base + c];
        v[u] = val;
        ss += val * val;
    }
    __shared__ float red1[256];
    red1[tid] = ss;
    __syncthreads();
    for (int s = 128; s > 0; s >>= 1) {
        if (tid < s) red1[tid] += red1[tid + s];
        __syncthreads();
    }
    float scale = rsqrtf(red1[0] / (float)H + EPSN);

    float part[E];
#pragma unroll
    for (int e = 0; e < E; e++) part[e] = 0.f;
#pragma unroll
    for (int u = 0; u < PER; u++) {
        int c = tid + u * 256;
        float o = v[u] * scale * w[c];
        v[u] = o;
        xh[base + c] = __float2half(o);
#pragma unroll
        for (int e = 0; e < E; e++) part[e] = fmaf(o, rw[c * E + e], part[e]);
    }
    __shared__ float red[256][E];
#pragma unroll
    for (int e = 0; e < E; e++) red[tid][e] = part[e];
    __syncthreads();
    for (int s = 128; s > 0; s >>= 1) {
        if (tid < s)
#pragma unroll
            for (int e = 0; e < E; e++) red[tid][e] += red[tid + s][e];
        __syncthreads();
    }
    __shared__ float s_scale;
    if (tid == 0) {
        float best = red[0][0]; int bi = 0;
        for (int e = 1; e < E; e++) if (red[0][e] > best) { best = red[0][e]; bi = e; }
        topidx[t] = bi;
        s_scale = 1.f / (1.f + expf(-best));
    }
    __syncthreads();
    float scv = s_scale;
#pragma unroll
    for (int u = 0; u < PER; u++) {
        int c = tid + u * 256;
        xwh[base + c] = __float2half(v[u] * scv);
    }

    __shared__ int s_last;
    __threadfence();
    if (tid == 0) {
        int old = atomicAdd(&g_sync, 1);
        s_last = (old == gridDim.x - 1) ? 1 : 0;
    }
    __syncthreads();
    if (!s_last) return;
    __threadfence();

    __shared__ int cnt[E], off[E], run[E];
    if (tid < E) { cnt[tid] = 0; run[tid] = 0; }
    __syncthreads();
    for (int tt = tid; tt < T; tt += 256) atomicAdd(&cnt[g_topidx[tt]], 1);
    __syncthreads();
    if (tid == 0) {
        int o = 0;
        for (int e = 0; e < E; e++) { off[e] = o; o += cnt[e]; }
        g_sync = 0;
    }
    __syncthreads();
    for (int tt = tid; tt < T; tt += 256) {
        int e = g_topidx[tt];
        int p = atomicAdd(&run[e], 1);
        g_perm[off[e] + p] = tt;
    }
    __syncthreads();
    if (tid < E) { g_cnt[tid] = cnt[tid]; g_off[tid] = off[tid]; }
}

/* ===================== rope + q/k rmsnorm + fp16, 2 heads per block ===================== */
__global__ void rope_cvt_kernel(const float* __restrict__ qkv, const int* __restrict__ positions,
                                __half* __restrict__ qh, __half* __restrict__ kh,
                                __half* __restrict__ vh)
{
    int t    = blockIdx.x;
    int half = threadIdx.x >> 7;
    int hh   = blockIdx.y * 2 + half;
    int d    = threadIdx.x & 127;
    const float* p = qkv + (size_t)t * QKVW + hh * HD;
    if (hh >= NH + NKV) {
        int kvh = hh - NH - NKV;
        vh[((size_t)kvh * T + t) * HD + d] = __float2half(p[d]);
        return;
    }
    float pos = (float)positions[t];
    int i = (d < 64) ? d : d - 64;
    float invf = powf(THETA_F, -(float)i / 64.f);
    float ang = pos * invf;
    float c = cosf(ang), s = sinf(ang);
    float x1 = p[i], x2 = p[i + 64];
    float val = (d < 64) ? (x1 * c - x2 * s) : (x2 * c + x1 * s);

    __shared__ float red[2][128];
    red[half][d] = val * val;
    __syncthreads();
    for (int st = 64; st > 0; st >>= 1) {
        if (d < st) red[half][d] += red[half][d + st];
        __syncthreads();
    }
    float scale = rsqrtf(red[half][0] / (float)HD + EPSN);
    val *= scale;
    if (hh < NH) qh[((size_t)t * NH + hh) * HD + d] = __float2half(val * ATTN_SCALE);
    else         kh[((size_t)(hh - NH) * T + t) * HD + d] = __float2half(val);
}

/* ===================== fp16 mma flash attention (causal, GQA) ===================== */
#define AROW 272
#define ATILE (64 * AROW)
#define ASMEM (5 * ATILE)

__global__ __launch_bounds__(128) void attn_mma_kernel(
    const __half* __restrict__ qh, const __half* __restrict__ kh,
    const __half* __restrict__ vh, __half* __restrict__ out)
{
    extern __shared__ __align__(16) char smem[];
    const int qb  = blockIdx.x;
    const int h   = blockIdx.y;
    const int kvh = h >> 2;
    const int tid = threadIdx.x;
    const int wq  = tid >> 5;
    const int lane = tid & 31;
    const int q0 = qb * 64;
    const int g2 = lane >> 3;

    uint32_t sb = smem_u32(smem);
    const uint32_t sK0 = sb + ATILE;
    const uint32_t sV0 = sb + 3 * ATILE;

    {
        const uint4* qg = (const uint4*)(qh + ((size_t)q0 * NH + h) * HD);
#pragma unroll
        for (int i = 0; i < 8; i++) {
            int idx = tid + i * 128;
            int row = idx >> 4, c = idx & 15;
            uint4 v = qg[(size_t)row * (NH * HD / 8) + c];
            *(uint4*)(smem + row * AROW + c * 16) = v;
        }
    }

    const char* kg = (const char*)(kh + (size_t)kvh * T * HD);
    const char* vg = (const char*)(vh + (size_t)kvh * T * HD);
    auto loadKV = [&](int kt, int s) {
        uint32_t dk = sK0 + (uint32_t)s * ATILE;
        uint32_t dv = sV0 + (uint32_t)s * ATILE;
        const char* kgt = kg + (size_t)kt * 64 * 256;
        const char* vgt = vg + (size_t)kt * 64 * 256;
#pragma unroll
        for (int i = 0; i < 8; i++) {
            int idx = tid + i * 128;
            int row = idx >> 4, c = idx & 15;
            uint32_t o = row * AROW + c * 16;
            int go = row * 256 + c * 16;
            CP16(dk + o, kgt + go, 16);
            CP16(dv + o, vgt + go, 16);
        }
    };

    loadKV(0, 0);
    asm volatile("cp.async.commit_group;" ::: "memory");
    __syncthreads();

    uint32_t aq[8][4];
    {
        uint32_t aOff = sb + (wq * 16 + (lane & 15)) * AROW + (lane >> 4) * 16;
#pragma unroll
        for (int kk = 0; kk < 8; kk++) ldm4(aq[kk], aOff + kk * 32);
    }

    float m0 = -1e30f, m1 = -1e30f, l0 = 0.f, l1 = 0.f;
    float o[16][4];
#pragma unroll
    for (int nt = 0; nt < 16; nt++)
#pragma unroll
        for (int q = 0; q < 4; q++) o[nt][q] = 0.f;

    const int ktmax = qb;
    for (int kt = 0; kt <= ktmax; kt++) {
        if (kt + 1 <= ktmax) loadKV(kt + 1, (kt + 1) & 1);
        asm volatile("cp.async.commit_group;" ::: "memory");
        if (kt == ktmax) asm volatile("cp.async.wait_group 0;" ::: "memory");
        else             asm volatile("cp.async.wait_group 1;" ::: "memory");
        __syncthreads();

        uint32_t kB = sK0 + (uint32_t)(kt & 1) * ATILE;
        uint32_t vB = sV0 + (uint32_t)(kt & 1) * ATILE;

        float sc[8][4];
#pragma unroll
        for (int nt = 0; nt < 8; nt++)
#pragma unroll
            for (int q = 0; q < 4; q++) sc[nt][q] = 0.f;

        uint32_t bOffK = kB + ((g2 >> 1) * 8 + (lane & 7)) * AROW + (g2 & 1) * 16;
#pragma unroll
        for (int kk = 0; kk < 8; kk++) {
            uint32_t kb[4][4];
#pragma unroll
            for (int p = 0; p < 4; p++)
                ldm4(kb[p], bOffK + p * (16 * AROW) + kk * 32);
#pragma unroll
            for (int p = 0; p < 4; p++) {
                mma_f16(sc[2 * p],     aq[kk], &kb[p][0]);
                mma_f16(sc[2 * p + 1], aq[kk], &kb[p][2]);
            }
        }

        int row0 = q0 + wq * 16 + (lane >> 2);
        if (kt == ktmax) {
            int colb = kt * 64 + 2 * (lane & 3);
#pragma unroll
            for (int nt = 0; nt < 8; nt++) {
                int c0 = colb + nt * 8;
                if (c0 > row0)         sc[nt][0] = -1e30f;
                if (c0 + 1 > row0)     sc[nt][1] = -1e30f;
                if (c0 > row0 + 8)     sc[nt][2] = -1e30f;
                if (c0 + 1 > row0 + 8) sc[nt][3] = -1e30f;
            }
        }

        float mt0 = -1e30f, mt1 = -1e30f;
#pragma unroll
        for (int nt = 0; nt < 8; nt++) {
            mt0 = fmaxf(mt0, fmaxf(sc[nt][0], sc[nt][1]));
            mt1 = fmaxf(mt1, fmaxf(sc[nt][2], sc[nt][3]));
        }
        mt0 = fmaxf(mt0, __shfl_xor_sync(0xffffffffu, mt0, 1));
        mt0 = fmaxf(mt0, __shfl_xor_sync(0xffffffffu, mt0, 2));
        mt1 = fmaxf(mt1, __shfl_xor_sync(0xffffffffu, mt1, 1));
        mt1 = fmaxf(mt1, __shfl_xor_sync(0xffffffffu, mt1, 2));
        float mn0 = fmaxf(m0, mt0), mn1 = fmaxf(m1, mt1);
        float al0 = __expf(m0 - mn0), al1 = __expf(m1 - mn1);
        m0 = mn0; m1 = mn1;
        float s0 = 0.f, s1 = 0.f;
#pragma unroll
        for (int nt = 0; nt < 8; nt++) {
            sc[nt][0] = __expf(sc[nt][0] - mn0);
            sc[nt][1] = __expf(sc[nt][1] - mn0);
            sc[nt][2] = __expf(sc[nt][2] - mn1);
            sc[nt][3] = __expf(sc[nt][3] - mn1);
            s0 += sc[nt][0] + sc[nt][1];
            s1 += sc[nt][2] + sc[nt][3];
        }
        s0 += __shfl_xor_sync(0xffffffffu, s0, 1);
        s0 += __shfl_xor_sync(0xffffffffu, s0, 2);
        s1 += __shfl_xor_sync(0xffffffffu, s1, 1);
        s1 += __shfl_xor_sync(0xffffffffu, s1, 2);
        l0 = l0 * al0 + s0;
        l1 = l1 * al1 + s1;
#pragma unroll
        for (int nt = 0; nt < 16; nt++) {
            o[nt][0] *= al0; o[nt][1] *= al0;
            o[nt][2] *= al1; o[nt][3] *= al1;
        }

        uint32_t bOffV = vB + ((g2 & 1) * 8 + (lane & 7)) * AROW + (g2 >> 1) * 16;
#pragma unroll
        for (int s = 0; s < 4; s++) {
            uint32_t ap[4];
            __half2 p0 = __floats2half2_rn(sc[2 * s][0],     sc[2 * s][1]);
            __half2 p1 = __floats2half2_rn(sc[2 * s][2],     sc[2 * s][3]);
            __half2 p2 = __floats2half2_rn(sc[2 * s + 1][0], sc[2 * s + 1][1]);
            __half2 p3 = __floats2half2_rn(sc[2 * s + 1][2], sc[2 * s + 1][3]);
            ap[0] = *(uint32_t*)&p0; ap[1] = *(uint32_t*)&p1;
            ap[2] = *(uint32_t*)&p2; ap[3] = *(uint32_t*)&p3;
#pragma unroll
            for (int p = 0; p < 8; p++) {
                uint32_t vb[4];
                ldm4t(vb, bOffV + s * (16 * AROW) + p * 32);
                mma_f16(o[2 * p],     ap, &vb[0]);
                mma_f16(o[2 * p + 1], ap, &vb[2]);
            }
        }
        __syncthreads();
    }

    float inv0 = 1.f / l0, inv1 = 1.f / l1;
    int orow = q0 + wq * 16 + (lane >> 2);
    __half* ob0 = out + (size_t)orow * H + h * HD + 2 * (lane & 3);
    __half* ob1 = ob0 + 8 * H;
#pragma unroll
    for (int nt = 0; nt < 16; nt++) {
        __half2 v0 = __floats2half2_rn(o[nt][0] * inv0, o[nt][1] * inv0);
        __half2 v1 = __floats2half2_rn(o[nt][2] * inv1, o[nt][3] * inv1);
        *(__half2*)(ob0 + nt * 8) = v0;
        *(__half2*)(ob1 + nt * 8) = v1;
    }
}

/* ===================== fp16 tensor-core GEMM core (4-stage A pipeline) ===================== */
#define ROWA 144
#define ASTG (128 * ROWA)
#define NSA  4
#define ROWB2 272
#define BSTG (64 * ROWB2)
#define GSMEM (512 + NSA * ASTG + 2 * BSTG)   /* 109056 */

__device__ __forceinline__ void gemm_core(
    const uint4* __restrict__ A4, const float4* __restrict__ Wf,
    float* __restrict__ C, __half* __restrict__ Ch, const float* __restrict__ addC,
    int N, int K, int accumulate, int n0, int m0,
    int use_perm, int cnt, int off, char* smem)
{
    const int tid = threadIdx.x;
    const int wid = tid >> 5;
    const int lane = tid & 31;
    const int warp_m = wid >> 1;
    const int warp_n = wid & 1;
    const int N4 = N >> 2;

    int* rows = (int*)smem;
    for (int i = tid; i < 128; i += 256)
        rows[i] = use_perm ? ((m0 + i < cnt) ? g_perm[off + m0 + i] : -1) : (m0 + i);
    __syncthreads();

    const uint32_t sb = smem_u32(smem);
    const uint32_t aBase = sb + 512;
    const uint32_t bBase = aBase + NSA * ASTG;
    const int K8 = K >> 3;
    const int nch = K >> 6;

    const int lrow = tid >> 1;
    const int cj = (tid & 1) * 4;
    int ra = rows[lrow];
    uint32_t szA = (ra >= 0) ? 16u : 0u;
    size_t ibA = (size_t)(ra >= 0 ? ra : 0) * K8 + cj;
    uint32_t dofA = (uint32_t)(lrow * ROWA + cj * 16);

    const int brow = tid >> 2;
    const int bq = tid & 3;
    const float4* wp0 = Wf + (size_t)brow * N4 + (n0 >> 2) + 2 * bq;
    const size_t wchunk = (size_t)64 * N4;
    uint32_t bsts = (uint32_t)(brow * ROWB2 + bq * 16);

    uint32_t aRowOff = (uint32_t)((warp_m * 32 + (lane & 15)) * ROWA + (lane >> 4) * 16);
    int g = lane >> 3;
    uint32_t bRowOff = (uint32_t)(((g & 1) * 8 + (lane & 7)) * ROWB2 +
                                  (warp_n * 64 + (g >> 1) * 8) * 2);

    float acc[2][8][4];
#pragma unroll
    for (int mt = 0; mt < 2; mt++)
#pragma unroll
        for (int nt = 0; nt < 8; nt++)
#pragma unroll
            for (int q = 0; q < 4; q++) acc[mt][nt][q] = 0.f;

    auto issueA = [&](int c) {
        uint32_t tb = aBase + (uint32_t)(c % NSA) * ASTG;
        size_t ko = (size_t)c * 8;
#pragma unroll
        for (int j2 = 0; j2 < 4; j2++)
            CP16(tb + dofA + j2 * 16, (const void*)(A4 + ibA + ko + j2), szA);
    };

    float4 br[8];
    auto ldgB = [&](int c) {
        const float4* wp = wp0 + (size_t)c * wchunk;
#pragma unroll
        for (int j2 = 0; j2 < 4; j2++) {
            br[2 * j2]     = wp[8 * j2];
            br[2 * j2 + 1] = wp[8 * j2 + 1];
        }
    };
    auto stsB = [&](int s) {
        uint32_t tb = bBase + (uint32_t)s * BSTG + bsts;
#pragma unroll
        for (int j2 = 0; j2 < 4; j2++) {
            uint4 pk = pack8h(br[2 * j2], br[2 * j2 + 1]);
            STS128(tb + j2 * 64, pk);
        }
    };

    /* prologue: 3 A chunks in flight */
    ldgB(0);
    issueA(0);
    asm volatile("cp.async.commit_group;" ::: "memory");
    if (nch > 1) issueA(1);
    asm volatile("cp.async.commit_group;" ::: "memory");
    if (nch > 2) issueA(2);
    asm volatile("cp.async.commit_group;" ::: "memory");

    for (int c = 0; c < nch; c++) {
        stsB(c & 1);
        if (c + 1 < nch) ldgB(c + 1);
        asm volatile("cp.async.wait_group 2;" ::: "memory");
        __syncthreads();
        if (c + 3 < nch) issueA(c + 3);
        asm volatile("cp.async.commit_group;" ::: "memory");

        uint32_t aB = aBase + (uint32_t)(c % NSA) * ASTG;
        uint32_t bB = bBase + (uint32_t)(c & 1) * BSTG;
#pragma unroll
        for (int kk = 0; kk < 4; kk++) {
            uint32_t ah[2][4];
            ldm4(ah[0], aB + aRowOff + kk * 32);
            ldm4(ah[1], aB + aRowOff + 2304 + kk * 32);
            uint32_t bh[4][4];
#pragma unroll
            for (int p = 0; p < 4; p++)
                ldm4t(bh[p], bB + bRowOff + kk * (16 * ROWB2) + p * 32);
#pragma unroll
            for (int mt = 0; mt < 2; mt++)
#pragma unroll
                for (int p = 0; p < 4; p++)
#pragma unroll
                    for (int hh = 0; hh < 2; hh++)
                        mma_f16(acc[mt][p * 2 + hh], ah[mt], &bh[p][hh * 2]);
        }
    }

    int lr = lane >> 2, lc = (lane & 3) * 2;
#pragma unroll
    for (int mt = 0; mt < 2; mt++) {
        int rloc = warp_m * 32 + mt * 16 + lr;
        int grow0 = rows[rloc];
        int grow1 = rows[rloc + 8];
#pragma unroll
        for (int nt = 0; nt < 8; nt++) {
            int col = n0 + warp_n * 64 + nt * 8 + lc;
            float* a4 = acc[mt][nt];
            if (Ch) {
                if (grow0 >= 0)
                    *(__half2*)(Ch + (size_t)grow0 * N + col) = __floats2half2_rn(a4[0], a4[1]);
                if (grow1 >= 0)
                    *(__half2*)(Ch + (size_t)grow1 * N + col) = __floats2half2_rn(a4[2], a4[3]);
            } else {
                if (grow0 >= 0) {
                    size_t cb = (size_t)grow0 * N + col;
                    if (accumulate) { C[cb] += a4[0]; C[cb + 1] += a4[1]; }
                    else if (addC)  { C[cb] = a4[0] + addC[cb]; C[cb + 1] = a4[1] + addC[cb + 1]; }
                    else            { C[cb] = a4[0]; C[cb + 1] = a4[1]; }
                }
                if (grow1 >= 0) {
                    size_t cb = (size_t)grow1 * N + col;
                    if (accumulate) { C[cb] += a4[2]; C[cb + 1] += a4[3]; }
                    else if (addC)  { C[cb] = a4[2] + addC[cb]; C[cb + 1] = a4[3] + addC[cb + 1]; }
                    else            { C[cb] = a4[2]; C[cb + 1] = a4[3]; }
                }
            }
        }
    }
}

/* generic GEMM (dense or grouped) — n-major grid */
__global__ __launch_bounds__(256, 2) void mma_gemm_kernel(
    const uint4* __restrict__ A4, const float4* __restrict__ Wf,
    float* __restrict__ C, __half* __restrict__ Ch, const float* __restrict__ addC,
    int N, int K, int accumulate, int grouped)
{
    extern __shared__ __align__(16) char smem[];
    const int n0 = blockIdx.x * 128;
    const int m0 = blockIdx.y * 128;
    int cnt = 0, off = 0;
    if (grouped) {
        cnt = g_cnt[blockIdx.z];
        off = g_off[blockIdx.z];
        if (m0 >= cnt) return;
        Wf += (size_t)blockIdx.z * K * (N >> 2);
    }
    gemm_core(A4, Wf, C, Ch, addC, N, K, accumulate, n0, m0, grouped, cnt, off, smem);
}

/* gate+up pairwise merge: x = n-tile + gate/up selector, y = m-tile */
__global__ __launch_bounds__(256, 2) void gateup2_kernel(
    const uint4* __restrict__ A4,
    const float4* __restrict__ Wg, const float4* __restrict__ Wu,
    __half* __restrict__ Gh, __half* __restrict__ Uh, int grouped)
{
    extern __shared__ __align__(16) char smem[];
    const int NXT = I_DIM / 128;   /* 32 */
    int is_up = blockIdx.x >= NXT;
    int n0 = (blockIdx.x - (is_up ? NXT : 0)) * 128;
    int m0 = blockIdx.y * 128;
    int cnt = 0, off = 0;
    const float4* Wf = is_up ? Wu : Wg;
    __half* Ch = is_up ? Uh : Gh;
    if (grouped) {
        cnt = g_cnt[blockIdx.z];
        off = g_off[blockIdx.z];
        if (m0 >= cnt) return;
        Wf += (size_t)blockIdx.z * H * (I_DIM >> 2);
    }
    gemm_core(A4, Wf, 0, Ch, 0, I_DIM, H, 0, n0, m0, grouped, cnt, off, smem);
}

/* ===================== fused silu for both paths (uint4 vectorized) ===================== */
__device__ __forceinline__ uint32_t silu_h2(uint32_t gbits, uint32_t ubits)
{
    __half2 g2 = *(__half2*)&gbits;
    __half2 u2 = *(__half2*)&ubits;
    float2 gv = __half22float2(g2);
    float2 uv = __half22float2(u2);
    __half2 r = __floats2half2_rn(gv.x / (1.f + __expf(-gv.x)) * uv.x,
                                  gv.y / (1.f + __expf(-gv.y)) * uv.y);
    return *(uint32_t*)&r;
}

__global__ void silu2_kernel(const uint4* __restrict__ gs, const uint4* __restrict__ us,
                             uint4* __restrict__ os,
                             const uint4* __restrict__ gr, const uint4* __restrict__ ur,
                             uint4* __restrict__ orr, int n4)
{
    int i = blockIdx.x * 256 + threadIdx.x;
    if (i >= n4) return;
    uint4 g = gs[i], u = us[i];
    uint4 r;
    r.x = silu_h2(g.x, u.x); r.y = silu_h2(g.y, u.y);
    r.z = silu_h2(g.z, u.z); r.w = silu_h2(g.w, u.w);
    os[i] = r;
    uint4 g2 = gr[i], u2 = ur[i];
    uint4 r2;
    r2.x = silu_h2(g2.x, u2.x); r2.y = silu_h2(g2.y, u2.y);
    r2.z = silu_h2(g2.z, u2.z); r2.w = silu_h2(g2.w, u2.w);
    orr[i] = r2;
}

/* ===================== launch ===================== */
extern "C" void kernel_launch(void* const* d_in, const int* in_sizes, int n_in,
                              void* d_out, int out_size)
{
    (void)in_sizes; (void)n_in; (void)out_size;
    const int*   positions = (const int*)d_in[0];
    const float* hidden    = (const float*)d_in[1];
    const float* residual  = (const float*)d_in[2];
    const float* ln1w      = (const float*)d_in[3];
    const float* ln2w      = (const float*)d_in[4];
    const float* w_qkv     = (const float*)d_in[5];
    const float* w_o       = (const float*)d_in[6];
    const float* router_w  = (const float*)d_in[7];
    const float* we_gate   = (const float*)d_in[8];
    const float* we_up     = (const float*)d_in[9];
    const float* we_down   = (const float*)d_in[10];
    const float* ws_gate   = (const float*)d_in[11];
    const float* ws_up     = (const float*)d_in[12];
    const float* ws_down   = (const float*)d_in[13];

    float* out  = (float*)d_out;
    float* res2 = out + (size_t)T * H;

    float *p_res, *p_qkv;
    int *p_top;
    uint4 *a1, *a2, *ghs, *uhs, *ghr, *uhr, *qh, *kh, *vh;
    cudaGetSymbolAddress((void**)&p_res,  g_res);
    cudaGetSymbolAddress((void**)&p_qkv,  g_qkv);
    cudaGetSymbolAddress((void**)&p_top,  g_topidx);
    cudaGetSymbolAddress((void**)&a1,  g_act1);
    cudaGetSymbolAddress((void**)&a2,  g_act2);
    cudaGetSymbolAddress((void**)&ghs, g_ghs);
    cudaGetSymbolAddress((void**)&uhs, g_uhs);
    cudaGetSymbolAddress((void**)&ghr, g_ghr);
    cudaGetSymbolAddress((void**)&uhr, g_uhr);
    cudaGetSymbolAddress((void**)&qh,  g_qh);
    cudaGetSymbolAddress((void**)&kh,  g_kh);
    cudaGetSymbolAddress((void**)&vh,  g_vh);
    __half* h1 = (__half*)a1;
    __half* h2 = (__half*)a2;

    cudaFuncSetAttribute(mma_gemm_kernel, cudaFuncAttributeMaxDynamicSharedMemorySize, GSMEM);
    cudaFuncSetAttribute(gateup2_kernel,  cudaFuncAttributeMaxDynamicSharedMemorySize, GSMEM);
    cudaFuncSetAttribute(attn_mma_kernel, cudaFuncAttributeMaxDynamicSharedMemorySize, ASMEM);

    /* 1. hs = hidden+residual ; res ; xh = rmsnorm (fp16) */
    addnorm_kernel<<<T, 256>>>(hidden, residual, ln1w, p_res, 0, h1);
    /* 2. qkv = x @ w_qkv (fp32 out for rope) */
    mma_gemm_kernel<<<dim3(QKVW/128, T/128, 1), 256, GSMEM>>>(a1, (const float4*)w_qkv, p_qkv, 0, 0, QKVW, H, 0, 0);
    /* 3. rope + qknorm + fp16 conversion (2 heads/block) */
    rope_cvt_kernel<<<dim3(T, (NH + 2*NKV)/2), 256>>>(p_qkv, positions, (__half*)qh, (__half*)kh, (__half*)vh);
    /* 4. fp16 mma attention -> h1 */
    attn_mma_kernel<<<dim3(T/64, NH), 128, ASMEM>>>((const __half*)qh, (const __half*)kh, (const __half*)vh, h1);
    /* 5. res2 = attn @ w_o + res */
    mma_gemm_kernel<<<dim3(H/128, T/128, 1), 256, GSMEM>>>(a1, (const float4*)w_o, res2, 0, p_res, H, H, 0, 0);
    /* 6+7+8. fused rmsnorm(res2) + router + last-block hist */
    addnorm_router_kernel<<<T, 256>>>(res2, ln2w, router_w, p_top, h1, h2);
    /* 9. shared gate+up (merged, dense, A=x2=h1) -> ghs/uhs */
    gateup2_kernel<<<dim3(2*I_DIM/128, T/128, 1), 256, GSMEM>>>(
        a1, (const float4*)ws_gate, (const float4*)ws_up, (__half*)ghs, (__half*)uhs, 0);
    /* 10. routed gate+up (merged, grouped, A=xw=h2) -> ghr/uhr */
    gateup2_kernel<<<dim3(2*I_DIM/128, T/128, E), 256, GSMEM>>>(
        a2, (const float4*)we_gate, (const float4*)we_up, (__half*)ghr, (__half*)uhr, 1);
    /* 11. single fused silu (vectorized): shared->h1, routed->h2 */
    silu2_kernel<<<((size_t)T*I_DIM/8 + 255)/256, 256>>>(
        ghs, uhs, a1, ghr, uhr, a2, T*I_DIM/8);
    /* 12. shared down -> out (write) */
    mma_gemm_kernel<<<dim3(H/128, T/128, 1), 256, GSMEM>>>(a1, (const float4*)ws_down, out, 0, 0, H, I_DIM, 0, 0);
    /* 13. routed down -> out (accumulate, grouped, A=h2) */
    mma_gemm_kernel<<<dim3(H/128, T/128, E), 256, GSMEM>>>(a2, (const float4*)we_down, out, 0, 0, H, I_DIM, 1, 1);
}

// round 17
// speedup vs baseline: 1.1245x; 1.1245x over previous
#include <cuda_runtime.h>
#include <cuda_fp16.h>
#include <math.h>
#include <stdint.h>

#define T    2048
#define H    2048
#define NH   16
#define NKV  4
#define HD   128
#define E    8
#define I_DIM 4096
#define QKVW ((NH + 2*NKV) * HD)   /* 3072 */
#define EPSN 1e-5f
#define THETA_F 500000.0f
#define ATTN_SCALE 0.08838834764831845f

/* ===================== scratch (device globals) ===================== */
__device__ float g_res [T*H];
__device__ float g_qkv [T*QKVW];
__device__ int   g_topidx[T];
__device__ int   g_perm[T];
__device__ int   g_cnt[E];
__device__ int   g_off[E];
__device__ int   g_sync;                      /* last-block counter (reset each call) */
/* fp16 buffers */
__device__ uint4 g_act1[(size_t)T*I_DIM/8];   /* x / attn-out / x2 / shared-silu */
__device__ uint4 g_act2[(size_t)T*I_DIM/8];   /* xw / routed-silu */
__device__ uint4 g_ghs[(size_t)T*I_DIM/8];    /* shared gate */
__device__ uint4 g_uhs[(size_t)T*I_DIM/8];    /* shared up */
__device__ uint4 g_ghr[(size_t)T*I_DIM/8];    /* routed gate */
__device__ uint4 g_uhr[(size_t)T*I_DIM/8];    /* routed up */
__device__ uint4 g_qh[(size_t)T*NH*HD/8];
__device__ uint4 g_kh[(size_t)NKV*T*HD/8];
__device__ uint4 g_vh[(size_t)NKV*T*HD/8];

/* ===================== small PTX wrappers ===================== */
__device__ __forceinline__ uint32_t smem_u32(const void* p) {
    uint32_t a;
    asm("{ .reg .u64 t; cvta.to.shared.u64 t, %1; cvt.u32.u64 %0, t; }" : "=r"(a) : "l"(p));
    return a;
}
__device__ __forceinline__ void ldm4(uint32_t* r, uint32_t addr) {
    asm volatile("ldmatrix.sync.aligned.m8n8.x4.shared.b16 {%0,%1,%2,%3}, [%4];"
        : "=r"(r[0]), "=r"(r[1]), "=r"(r[2]), "=r"(r[3]) : "r"(addr));
}
__device__ __forceinline__ void ldm4t(uint32_t* r, uint32_t addr) {
    asm volatile("ldmatrix.sync.aligned.m8n8.x4.trans.shared.b16 {%0,%1,%2,%3}, [%4];"
        : "=r"(r[0]), "=r"(r[1]), "=r"(r[2]), "=r"(r[3]) : "r"(addr));
}
__device__ __forceinline__ void mma_f16(float* c, const uint32_t* a, const uint32_t* b) {
    asm volatile(
        "mma.sync.aligned.m16n8k16.row.col.f32.f16.f16.f32 "
        "{%0,%1,%2,%3}, {%4,%5,%6,%7}, {%8,%9}, {%0,%1,%2,%3};"
        : "+f"(c[0]), "+f"(c[1]), "+f"(c[2]), "+f"(c[3])
        : "r"(a[0]), "r"(a[1]), "r"(a[2]), "r"(a[3]), "r"(b[0]), "r"(b[1]));
}
#define CP16(dst, src, sz) asm volatile("cp.async.cg.shared.global [%0], [%1], 16, %2;" :: "r"(dst), "l"(src), "r"(sz) : "memory")
#define STS128(addr, v) asm volatile("st.shared.v4.b32 [%0], {%1,%2,%3,%4};" :: "r"(addr), "r"((v).x), "r"((v).y), "r"((v).z), "r"((v).w) : "memory")

__device__ __forceinline__ uint4 pack8h(float4 a, float4 b) {
    __half2 h0 = __floats2half2_rn(a.x, a.y);
    __half2 h1 = __floats2half2_rn(a.z, a.w);
    __half2 h2 = __floats2half2_rn(b.x, b.y);
    __half2 h3 = __floats2half2_rn(b.z, b.w);
    uint4 r;
    r.x = *(uint32_t*)&h0; r.y = *(uint32_t*)&h1;
    r.z = *(uint32_t*)&h2; r.w = *(uint32_t*)&h3;
    return r;
}

/* ===================== add + rmsnorm ===================== */
__global__ void addnorm_kernel(const float* __restrict__ a, const float* __restrict__ b,
                               const float* __restrict__ w, float* __restrict__ res,
                               float* __restrict__ xout, __half* __restrict__ xh)
{
    int t = blockIdx.x;
    int tid = threadIdx.x;
    const int PER = H / 256;
    size_t base = (size_t)t * H;
    float v[PER];
    float ss = 0.f;
#pragma unroll
    for (int u = 0; u < PER; u++) {
        int c = tid + u * 256;
        float val = a[base + c];
        if (b) val += b[base + c];
        v[u] = val;
        if (res) res[base + c] = val;
        ss += val * val;
    }
    __shared__ float red[256];
    red[tid] = ss;
    __syncthreads();
    for (int s = 128; s > 0; s >>= 1) {
        if (tid < s) red[tid] += red[tid + s];
        __syncthreads();
    }
    float scale = rsqrtf(red[0] / (float)H + EPSN);
#pragma unroll
    for (int u = 0; u < PER; u++) {
        int c = tid + u * 256;
        float o = v[u] * scale * w[c];
        if (xout) xout[base + c] = o;
        xh[base + c] = __float2half(o);
    }
}

/* ===================== fused rmsnorm(step6) + router + last-block hist ===================== */
__global__ void addnorm_router_kernel(const float* __restrict__ a,
                                      const float* __restrict__ w,
                                      const float* __restrict__ rw,
                                      int* __restrict__ topidx,
                                      __half* __restrict__ xh,
                                      __half* __restrict__ xwh)
{
    int t = blockIdx.x;
    int tid = threadIdx.x;
    const int PER = H / 256;
    size_t base = (size_t)t * H;
    float v[PER];
    float ss = 0.f;
#pragma unroll
    for (int u = 0; u < PER; u++) {
        int c = tid + u * 256;
        float val = a[base + c];
        v[u] = val;
        ss += val * val;
    }
    __shared__ float red1[256];
    red1[tid] = ss;
    __syncthreads();
    for (int s = 128; s > 0; s >>= 1) {
        if (tid < s) red1[tid] += red1[tid + s];
        __syncthreads();
    }
    float scale = rsqrtf(red1[0] / (float)H + EPSN);

    float part[E];
#pragma unroll
    for (int e = 0; e < E; e++) part[e] = 0.f;
#pragma unroll
    for (int u = 0; u < PER; u++) {
        int c = tid + u * 256;
        float o = v[u] * scale * w[c];
        v[u] = o;
        xh[base + c] = __float2half(o);
#pragma unroll
        for (int e = 0; e < E; e++) part[e] = fmaf(o, rw[c * E + e], part[e]);
    }
    __shared__ float red[256][E];
#pragma unroll
    for (int e = 0; e < E; e++) red[tid][e] = part[e];
    __syncthreads();
    for (int s = 128; s > 0; s >>= 1) {
        if (tid < s)
#pragma unroll
            for (int e = 0; e < E; e++) red[tid][e] += red[tid + s][e];
        __syncthreads();
    }
    __shared__ float s_scale;
    if (tid == 0) {
        float best = red[0][0]; int bi = 0;
        for (int e = 1; e < E; e++) if (red[0][e] > best) { best = red[0][e]; bi = e; }
        topidx[t] = bi;
        s_scale = 1.f / (1.f + expf(-best));
    }
    __syncthreads();
    float scv = s_scale;
#pragma unroll
    for (int u = 0; u < PER; u++) {
        int c = tid + u * 256;
        xwh[base + c] = __float2half(v[u] * scv);
    }

    __shared__ int s_last;
    __threadfence();
    if (tid == 0) {
        int old = atomicAdd(&g_sync, 1);
        s_last = (old == gridDim.x - 1) ? 1 : 0;
    }
    __syncthreads();
    if (!s_last) return;
    __threadfence();

    __shared__ int cnt[E], off[E], run[E];
    if (tid < E) { cnt[tid] = 0; run[tid] = 0; }
    __syncthreads();
    for (int tt = tid; tt < T; tt += 256) atomicAdd(&cnt[g_topidx[tt]], 1);
    __syncthreads();
    if (tid == 0) {
        int o = 0;
        for (int e = 0; e < E; e++) { off[e] = o; o += cnt[e]; }
        g_sync = 0;
    }
    __syncthreads();
    for (int tt = tid; tt < T; tt += 256) {
        int e = g_topidx[tt];
        int p = atomicAdd(&run[e], 1);
        g_perm[off[e] + p] = tt;
    }
    __syncthreads();
    if (tid < E) { g_cnt[tid] = cnt[tid]; g_off[tid] = off[tid]; }
}

/* ===================== rope + q/k rmsnorm + fp16, 2 heads per block ===================== */
__global__ void rope_cvt_kernel(const float* __restrict__ qkv, const int* __restrict__ positions,
                                __half* __restrict__ qh, __half* __restrict__ kh,
                                __half* __restrict__ vh)
{
    int t    = blockIdx.x;
    int half = threadIdx.x >> 7;
    int hh   = blockIdx.y * 2 + half;
    int d    = threadIdx.x & 127;
    const float* p = qkv + (size_t)t * QKVW + hh * HD;
    if (hh >= NH + NKV) {
        int kvh = hh - NH - NKV;
        vh[((size_t)kvh * T + t) * HD + d] = __float2half(p[d]);
        return;
    }
    float pos = (float)positions[t];
    int i = (d < 64) ? d : d - 64;
    float invf = powf(THETA_F, -(float)i / 64.f);
    float ang = pos * invf;
    float c = cosf(ang), s = sinf(ang);
    float x1 = p[i], x2 = p[i + 64];
    float val = (d < 64) ? (x1 * c - x2 * s) : (x2 * c + x1 * s);

    __shared__ float red[2][128];
    red[half][d] = val * val;
    __syncthreads();
    for (int st = 64; st > 0; st >>= 1) {
        if (d < st) red[half][d] += red[half][d + st];
        __syncthreads();
    }
    float scale = rsqrtf(red[half][0] / (float)HD + EPSN);
    val *= scale;
    if (hh < NH) qh[((size_t)t * NH + hh) * HD + d] = __float2half(val * ATTN_SCALE);
    else         kh[((size_t)(hh - NH) * T + t) * HD + d] = __float2half(val);
}

/* ===================== fp16 mma flash attention (causal, GQA) ===================== */
#define AROW 272
#define ATILE (64 * AROW)
#define ASMEM (5 * ATILE)

__global__ __launch_bounds__(128) void attn_mma_kernel(
    const __half* __restrict__ qh, const __half* __restrict__ kh,
    const __half* __restrict__ vh, __half* __restrict__ out)
{
    extern __shared__ __align__(16) char smem[];
    const int qb  = blockIdx.x;
    const int h   = blockIdx.y;
    const int kvh = h >> 2;
    const int tid = threadIdx.x;
    const int wq  = tid >> 5;
    const int lane = tid & 31;
    const int q0 = qb * 64;
    const int g2 = lane >> 3;

    uint32_t sb = smem_u32(smem);
    const uint32_t sK0 = sb + ATILE;
    const uint32_t sV0 = sb + 3 * ATILE;

    {
        const uint4* qg = (const uint4*)(qh + ((size_t)q0 * NH + h) * HD);
#pragma unroll
        for (int i = 0; i < 8; i++) {
            int idx = tid + i * 128;
            int row = idx >> 4, c = idx & 15;
            uint4 v = qg[(size_t)row * (NH * HD / 8) + c];
            *(uint4*)(smem + row * AROW + c * 16) = v;
        }
    }

    const char* kg = (const char*)(kh + (size_t)kvh * T * HD);
    const char* vg = (const char*)(vh + (size_t)kvh * T * HD);
    auto loadKV = [&](int kt, int s) {
        uint32_t dk = sK0 + (uint32_t)s * ATILE;
        uint32_t dv = sV0 + (uint32_t)s * ATILE;
        const char* kgt = kg + (size_t)kt * 64 * 256;
        const char* vgt = vg + (size_t)kt * 64 * 256;
#pragma unroll
        for (int i = 0; i < 8; i++) {
            int idx = tid + i * 128;
            int row = idx >> 4, c = idx & 15;
            uint32_t o = row * AROW + c * 16;
            int go = row * 256 + c * 16;
            CP16(dk + o, kgt + go, 16);
            CP16(dv + o, vgt + go, 16);
        }
    };

    loadKV(0, 0);
    asm volatile("cp.async.commit_group;" ::: "memory");
    __syncthreads();

    uint32_t aq[8][4];
    {
        uint32_t aOff = sb + (wq * 16 + (lane & 15)) * AROW + (lane >> 4) * 16;
#pragma unroll
        for (int kk = 0; kk < 8; kk++) ldm4(aq[kk], aOff + kk * 32);
    }

    float m0 = -1e30f, m1 = -1e30f, l0 = 0.f, l1 = 0.f;
    float o[16][4];
#pragma unroll
    for (int nt = 0; nt < 16; nt++)
#pragma unroll
        for (int q = 0; q < 4; q++) o[nt][q] = 0.f;

    const int ktmax = qb;
    for (int kt = 0; kt <= ktmax; kt++) {
        if (kt + 1 <= ktmax) loadKV(kt + 1, (kt + 1) & 1);
        asm volatile("cp.async.commit_group;" ::: "memory");
        if (kt == ktmax) asm volatile("cp.async.wait_group 0;" ::: "memory");
        else             asm volatile("cp.async.wait_group 1;" ::: "memory");
        __syncthreads();

        uint32_t kB = sK0 + (uint32_t)(kt & 1) * ATILE;
        uint32_t vB = sV0 + (uint32_t)(kt & 1) * ATILE;

        float sc[8][4];
#pragma unroll
        for (int nt = 0; nt < 8; nt++)
#pragma unroll
            for (int q = 0; q < 4; q++) sc[nt][q] = 0.f;

        uint32_t bOffK = kB + ((g2 >> 1) * 8 + (lane & 7)) * AROW + (g2 & 1) * 16;
#pragma unroll
        for (int kk = 0; kk < 8; kk++) {
            uint32_t kb[4][4];
#pragma unroll
            for (int p = 0; p < 4; p++)
                ldm4(kb[p], bOffK + p * (16 * AROW) + kk * 32);
#pragma unroll
            for (int p = 0; p < 4; p++) {
                mma_f16(sc[2 * p],     aq[kk], &kb[p][0]);
                mma_f16(sc[2 * p + 1], aq[kk], &kb[p][2]);
            }
        }

        int row0 = q0 + wq * 16 + (lane >> 2);
        if (kt == ktmax) {
            int colb = kt * 64 + 2 * (lane & 3);
#pragma unroll
            for (int nt = 0; nt < 8; nt++) {
                int c0 = colb + nt * 8;
                if (c0 > row0)         sc[nt][0] = -1e30f;
                if (c0 + 1 > row0)     sc[nt][1] = -1e30f;
                if (c0 > row0 + 8)     sc[nt][2] = -1e30f;
                if (c0 + 1 > row0 + 8) sc[nt][3] = -1e30f;
            }
        }

        float mt0 = -1e30f, mt1 = -1e30f;
#pragma unroll
        for (int nt = 0; nt < 8; nt++) {
            mt0 = fmaxf(mt0, fmaxf(sc[nt][0], sc[nt][1]));
            mt1 = fmaxf(mt1, fmaxf(sc[nt][2], sc[nt][3]));
        }
        mt0 = fmaxf(mt0, __shfl_xor_sync(0xffffffffu, mt0, 1));
        mt0 = fmaxf(mt0, __shfl_xor_sync(0xffffffffu, mt0, 2));
        mt1 = fmaxf(mt1, __shfl_xor_sync(0xffffffffu, mt1, 1));
        mt1 = fmaxf(mt1, __shfl_xor_sync(0xffffffffu, mt1, 2));
        float mn0 = fmaxf(m0, mt0), mn1 = fmaxf(m1, mt1);
        float al0 = __expf(m0 - mn0), al1 = __expf(m1 - mn1);
        m0 = mn0; m1 = mn1;
        float s0 = 0.f, s1 = 0.f;
#pragma unroll
        for (int nt = 0; nt < 8; nt++) {
            sc[nt][0] = __expf(sc[nt][0] - mn0);
            sc[nt][1] = __expf(sc[nt][1] - mn0);
            sc[nt][2] = __expf(sc[nt][2] - mn1);
            sc[nt][3] = __expf(sc[nt][3] - mn1);
            s0 += sc[nt][0] + sc[nt][1];
            s1 += sc[nt][2] + sc[nt][3];
        }
        s0 += __shfl_xor_sync(0xffffffffu, s0, 1);
        s0 += __shfl_xor_sync(0xffffffffu, s0, 2);
        s1 += __shfl_xor_sync(0xffffffffu, s1, 1);
        s1 += __shfl_xor_sync(0xffffffffu, s1, 2);
        l0 = l0 * al0 + s0;
        l1 = l1 * al1 + s1;
#pragma unroll
        for (int nt = 0; nt < 16; nt++) {
            o[nt][0] *= al0; o[nt][1] *= al0;
            o[nt][2] *= al1; o[nt][3] *= al1;
        }

        uint32_t bOffV = vB + ((g2 & 1) * 8 + (lane & 7)) * AROW + (g2 >> 1) * 16;
#pragma unroll
        for (int s = 0; s < 4; s++) {
            uint32_t ap[4];
            __half2 p0 = __floats2half2_rn(sc[2 * s][0],     sc[2 * s][1]);
            __half2 p1 = __floats2half2_rn(sc[2 * s][2],     sc[2 * s][3]);
            __half2 p2 = __floats2half2_rn(sc[2 * s + 1][0], sc[2 * s + 1][1]);
            __half2 p3 = __floats2half2_rn(sc[2 * s + 1][2], sc[2 * s + 1][3]);
            ap[0] = *(uint32_t*)&p0; ap[1] = *(uint32_t*)&p1;
            ap[2] = *(uint32_t*)&p2; ap[3] = *(uint32_t*)&p3;
#pragma unroll
            for (int p = 0; p < 8; p++) {
                uint32_t vb[4];
                ldm4t(vb, bOffV + s * (16 * AROW) + p * 32);
                mma_f16(o[2 * p],     ap, &vb[0]);
                mma_f16(o[2 * p + 1], ap, &vb[2]);
            }
        }
        __syncthreads();
    }

    float inv0 = 1.f / l0, inv1 = 1.f / l1;
    int orow = q0 + wq * 16 + (lane >> 2);
    __half* ob0 = out + (size_t)orow * H + h * HD + 2 * (lane & 3);
    __half* ob1 = ob0 + 8 * H;
#pragma unroll
    for (int nt = 0; nt < 16; nt++) {
        __half2 v0 = __floats2half2_rn(o[nt][0] * inv0, o[nt][1] * inv0);
        __half2 v1 = __floats2half2_rn(o[nt][2] * inv1, o[nt][3] * inv1);
        *(__half2*)(ob0 + nt * 8) = v0;
        *(__half2*)(ob1 + nt * 8) = v1;
    }
}

/* ===================== fp16 tensor-core GEMM core (3-stage, 2 CTAs/SM) ===================== */
#define ROWA 144
#define ASTG (128 * ROWA)
#define NSA  3
#define ROWB2 272
#define BSTG (64 * ROWB2)
#define GSMEM (512 + NSA * ASTG + 2 * BSTG)   /* 90624 -> 2 CTAs/SM fits */

__device__ __forceinline__ void gemm_core(
    const uint4* __restrict__ A4, const float4* __restrict__ Wf,
    float* __restrict__ C, __half* __restrict__ Ch, const float* __restrict__ addC,
    int N, int K, int accumulate, int n0, int m0,
    int use_perm, int cnt, int off, char* smem)
{
    const int tid = threadIdx.x;
    const int wid = tid >> 5;
    const int lane = tid & 31;
    const int warp_m = wid >> 1;
    const int warp_n = wid & 1;
    const int N4 = N >> 2;

    int* rows = (int*)smem;
    for (int i = tid; i < 128; i += 256)
        rows[i] = use_perm ? ((m0 + i < cnt) ? g_perm[off + m0 + i] : -1) : (m0 + i);
    __syncthreads();

    const uint32_t sb = smem_u32(smem);
    const uint32_t aBase = sb + 512;
    const uint32_t bBase = aBase + NSA * ASTG;
    const int K8 = K >> 3;
    const int nch = K >> 6;

    const int lrow = tid >> 1;
    const int cj = (tid & 1) * 4;
    int ra = rows[lrow];
    uint32_t szA = (ra >= 0) ? 16u : 0u;
    size_t ibA = (size_t)(ra >= 0 ? ra : 0) * K8 + cj;
    uint32_t dofA = (uint32_t)(lrow * ROWA + cj * 16);

    const int brow = tid >> 2;
    const int bq = tid & 3;
    const float4* wp0 = Wf + (size_t)brow * N4 + (n0 >> 2) + 2 * bq;
    const size_t wchunk = (size_t)64 * N4;
    uint32_t bsts = (uint32_t)(brow * ROWB2 + bq * 16);

    uint32_t aRowOff = (uint32_t)((warp_m * 32 + (lane & 15)) * ROWA + (lane >> 4) * 16);
    int g = lane >> 3;
    uint32_t bRowOff = (uint32_t)(((g & 1) * 8 + (lane & 7)) * ROWB2 +
                                  (warp_n * 64 + (g >> 1) * 8) * 2);

    float acc[2][8][4];
#pragma unroll
    for (int mt = 0; mt < 2; mt++)
#pragma unroll
        for (int nt = 0; nt < 8; nt++)
#pragma unroll
            for (int q = 0; q < 4; q++) acc[mt][nt][q] = 0.f;

    auto issueA = [&](int c) {
        uint32_t tb = aBase + (uint32_t)(c % NSA) * ASTG;
        size_t ko = (size_t)c * 8;
#pragma unroll
        for (int j2 = 0; j2 < 4; j2++)
            CP16(tb + dofA + j2 * 16, (const void*)(A4 + ibA + ko + j2), szA);
    };

    float4 br[8];
    auto ldgB = [&](int c) {
        const float4* wp = wp0 + (size_t)c * wchunk;
#pragma unroll
        for (int j2 = 0; j2 < 4; j2++) {
            br[2 * j2]     = wp[8 * j2];
            br[2 * j2 + 1] = wp[8 * j2 + 1];
        }
    };
    auto stsB = [&](int s) {
        uint32_t tb = bBase + (uint32_t)s * BSTG + bsts;
#pragma unroll
        for (int j2 = 0; j2 < 4; j2++) {
            uint4 pk = pack8h(br[2 * j2], br[2 * j2 + 1]);
            STS128(tb + j2 * 64, pk);
        }
    };

    ldgB(0);
    issueA(0);
    asm volatile("cp.async.commit_group;" ::: "memory");
    if (nch > 1) issueA(1);
    asm volatile("cp.async.commit_group;" ::: "memory");

    for (int c = 0; c < nch; c++) {
        stsB(c & 1);
        if (c + 1 < nch) ldgB(c + 1);
        asm volatile("cp.async.wait_group 1;" ::: "memory");
        __syncthreads();
        if (c + 2 < nch) issueA(c + 2);
        asm volatile("cp.async.commit_group;" ::: "memory");

        uint32_t aB = aBase + (uint32_t)(c % NSA) * ASTG;
        uint32_t bB = bBase + (uint32_t)(c & 1) * BSTG;
#pragma unroll
        for (int kk = 0; kk < 4; kk++) {
            uint32_t ah[2][4];
            ldm4(ah[0], aB + aRowOff + kk * 32);
            ldm4(ah[1], aB + aRowOff + 2304 + kk * 32);
            uint32_t bh[4][4];
#pragma unroll
            for (int p = 0; p < 4; p++)
                ldm4t(bh[p], bB + bRowOff + kk * (16 * ROWB2) + p * 32);
#pragma unroll
            for (int mt = 0; mt < 2; mt++)
#pragma unroll
                for (int p = 0; p < 4; p++)
#pragma unroll
                    for (int hh = 0; hh < 2; hh++)
                        mma_f16(acc[mt][p * 2 + hh], ah[mt], &bh[p][hh * 2]);
        }
    }

    int lr = lane >> 2, lc = (lane & 3) * 2;
#pragma unroll
    for (int mt = 0; mt < 2; mt++) {
        int rloc = warp_m * 32 + mt * 16 + lr;
        int grow0 = rows[rloc];
        int grow1 = rows[rloc + 8];
#pragma unroll
        for (int nt = 0; nt < 8; nt++) {
            int col = n0 + warp_n * 64 + nt * 8 + lc;
            float* a4 = acc[mt][nt];
            if (Ch) {
                if (grow0 >= 0)
                    *(__half2*)(Ch + (size_t)grow0 * N + col) = __floats2half2_rn(a4[0], a4[1]);
                if (grow1 >= 0)
                    *(__half2*)(Ch + (size_t)grow1 * N + col) = __floats2half2_rn(a4[2], a4[3]);
            } else {
                if (grow0 >= 0) {
                    size_t cb = (size_t)grow0 * N + col;
                    if (accumulate) { C[cb] += a4[0]; C[cb + 1] += a4[1]; }
                    else if (addC)  { C[cb] = a4[0] + addC[cb]; C[cb + 1] = a4[1] + addC[cb + 1]; }
                    else            { C[cb] = a4[0]; C[cb + 1] = a4[1]; }
                }
                if (grow1 >= 0) {
                    size_t cb = (size_t)grow1 * N + col;
                    if (accumulate) { C[cb] += a4[2]; C[cb + 1] += a4[3]; }
                    else if (addC)  { C[cb] = a4[2] + addC[cb]; C[cb + 1] = a4[3] + addC[cb + 1]; }
                    else            { C[cb] = a4[2]; C[cb + 1] = a4[3]; }
                }
            }
        }
    }
}

/* generic GEMM (dense or grouped) — n-major grid */
__global__ __launch_bounds__(256, 2) void mma_gemm_kernel(
    const uint4* __restrict__ A4, const float4* __restrict__ Wf,
    float* __restrict__ C, __half* __restrict__ Ch, const float* __restrict__ addC,
    int N, int K, int accumulate, int grouped)
{
    extern __shared__ __align__(16) char smem[];
    const int n0 = blockIdx.x * 128;
    const int m0 = blockIdx.y * 128;
    int cnt = 0, off = 0;
    if (grouped) {
        cnt = g_cnt[blockIdx.z];
        off = g_off[blockIdx.z];
        if (m0 >= cnt) return;
        Wf += (size_t)blockIdx.z * K * (N >> 2);
    }
    gemm_core(A4, Wf, C, Ch, addC, N, K, accumulate, n0, m0, grouped, cnt, off, smem);
}

/* gate+up pairwise merge: x = n-tile + gate/up selector, y = m-tile */
__global__ __launch_bounds__(256, 2) void gateup2_kernel(
    const uint4* __restrict__ A4,
    const float4* __restrict__ Wg, const float4* __restrict__ Wu,
    __half* __restrict__ Gh, __half* __restrict__ Uh, int grouped)
{
    extern __shared__ __align__(16) char smem[];
    const int NXT = I_DIM / 128;   /* 32 */
    int is_up = blockIdx.x >= NXT;
    int n0 = (blockIdx.x - (is_up ? NXT : 0)) * 128;
    int m0 = blockIdx.y * 128;
    int cnt = 0, off = 0;
    const float4* Wf = is_up ? Wu : Wg;
    __half* Ch = is_up ? Uh : Gh;
    if (grouped) {
        cnt = g_cnt[blockIdx.z];
        off = g_off[blockIdx.z];
        if (m0 >= cnt) return;
        Wf += (size_t)blockIdx.z * H * (I_DIM >> 2);
    }
    gemm_core(A4, Wf, 0, Ch, 0, I_DIM, H, 0, n0, m0, grouped, cnt, off, smem);
}

/* ===================== fused silu for both paths (uint4 vectorized) ===================== */
__device__ __forceinline__ uint32_t silu_h2(uint32_t gbits, uint32_t ubits)
{
    __half2 g2 = *(__half2*)&gbits;
    __half2 u2 = *(__half2*)&ubits;
    float2 gv = __half22float2(g2);
    float2 uv = __half22float2(u2);
    __half2 r = __floats2half2_rn(gv.x / (1.f + __expf(-gv.x)) * uv.x,
                                  gv.y / (1.f + __expf(-gv.y)) * uv.y);
    return *(uint32_t*)&r;
}

__global__ void silu2_kernel(const uint4* __restrict__ gs, const uint4* __restrict__ us,
                             uint4* __restrict__ os,
                             const uint4* __restrict__ gr, const uint4* __restrict__ ur,
                             uint4* __restrict__ orr, int n4)
{
    int i = blockIdx.x * 256 + threadIdx.x;
    if (i >= n4) return;
    uint4 g = gs[i], u = us[i];
    uint4 r;
    r.x = silu_h2(g.x, u.x); r.y = silu_h2(g.y, u.y);
    r.z = silu_h2(g.z, u.z); r.w = silu_h2(g.w, u.w);
    os[i] = r;
    uint4 g2 = gr[i], u2 = ur[i];
    uint4 r2;
    r2.x = silu_h2(g2.x, u2.x); r2.y = silu_h2(g2.y, u2.y);
    r2.z = silu_h2(g2.z, u2.z); r2.w = silu_h2(g2.w, u2.w);
    orr[i] = r2;
}

/* ===================== launch ===================== */
extern "C" void kernel_launch(void* const* d_in, const int* in_sizes, int n_in,
                              void* d_out, int out_size)
{
    (void)in_sizes; (void)n_in; (void)out_size;
    const int*   positions = (const int*)d_in[0];
    const float* hidden    = (const float*)d_in[1];
    const float* residual  = (const float*)d_in[2];
    const float* ln1w      = (const float*)d_in[3];
    const float* ln2w      = (const float*)d_in[4];
    const float* w_qkv     = (const float*)d_in[5];
    const float* w_o       = (const float*)d_in[6];
    const float* router_w  = (const float*)d_in[7];
    const float* we_gate   = (const float*)d_in[8];
    const float* we_up     = (const float*)d_in[9];
    const float* we_down   = (const float*)d_in[10];
    const float* ws_gate   = (const float*)d_in[11];
    const float* ws_up     = (const float*)d_in[12];
    const float* ws_down   = (const float*)d_in[13];

    float* out  = (float*)d_out;
    float* res2 = out + (size_t)T * H;

    float *p_res, *p_qkv;
    int *p_top;
    uint4 *a1, *a2, *ghs, *uhs, *ghr, *uhr, *qh, *kh, *vh;
    cudaGetSymbolAddress((void**)&p_res,  g_res);
    cudaGetSymbolAddress((void**)&p_qkv,  g_qkv);
    cudaGetSymbolAddress((void**)&p_top,  g_topidx);
    cudaGetSymbolAddress((void**)&a1,  g_act1);
    cudaGetSymbolAddress((void**)&a2,  g_act2);
    cudaGetSymbolAddress((void**)&ghs, g_ghs);
    cudaGetSymbolAddress((void**)&uhs, g_uhs);
    cudaGetSymbolAddress((void**)&ghr, g_ghr);
    cudaGetSymbolAddress((void**)&uhr, g_uhr);
    cudaGetSymbolAddress((void**)&qh,  g_qh);
    cudaGetSymbolAddress((void**)&kh,  g_kh);
    cudaGetSymbolAddress((void**)&vh,  g_vh);
    __half* h1 = (__half*)a1;
    __half* h2 = (__half*)a2;

    cudaFuncSetAttribute(mma_gemm_kernel, cudaFuncAttributeMaxDynamicSharedMemorySize, GSMEM);
    cudaFuncSetAttribute(gateup2_kernel,  cudaFuncAttributeMaxDynamicSharedMemorySize, GSMEM);
    cudaFuncSetAttribute(attn_mma_kernel, cudaFuncAttributeMaxDynamicSharedMemorySize, ASMEM);

    /* 1. hs = hidden+residual ; res ; xh = rmsnorm (fp16) */
    addnorm_kernel<<<T, 256>>>(hidden, residual, ln1w, p_res, 0, h1);
    /* 2. qkv = x @ w_qkv (fp32 out for rope) */
    mma_gemm_kernel<<<dim3(QKVW/128, T/128, 1), 256, GSMEM>>>(a1, (const float4*)w_qkv, p_qkv, 0, 0, QKVW, H, 0, 0);
    /* 3. rope + qknorm + fp16 conversion (2 heads/block) */
    rope_cvt_kernel<<<dim3(T, (NH + 2*NKV)/2), 256>>>(p_qkv, positions, (__half*)qh, (__half*)kh, (__half*)vh);
    /* 4. fp16 mma attention -> h1 */
    attn_mma_kernel<<<dim3(T/64, NH), 128, ASMEM>>>((const __half*)qh, (const __half*)kh, (const __half*)vh, h1);
    /* 5. res2 = attn @ w_o + res */
    mma_gemm_kernel<<<dim3(H/128, T/128, 1), 256, GSMEM>>>(a1, (const float4*)w_o, res2, 0, p_res, H, H, 0, 0);
    /* 6+7+8. fused rmsnorm(res2) + router + last-block hist */
    addnorm_router_kernel<<<T, 256>>>(res2, ln2w, router_w, p_top, h1, h2);
    /* 9. shared gate+up (merged, dense, A=x2=h1) -> ghs/uhs */
    gateup2_kernel<<<dim3(2*I_DIM/128, T/128, 1), 256, GSMEM>>>(
        a1, (const float4*)ws_gate, (const float4*)ws_up, (__half*)ghs, (__half*)uhs, 0);
    /* 10. routed gate+up (merged, grouped, A=xw=h2) -> ghr/uhr */
    gateup2_kernel<<<dim3(2*I_DIM/128, T/128, E), 256, GSMEM>>>(
        a2, (const float4*)we_gate, (const float4*)we_up, (__half*)ghr, (__half*)uhr, 1);
    /* 11. single fused silu (vectorized): shared->h1, routed->h2 */
    silu2_kernel<<<((size_t)T*I_DIM/8 + 255)/256, 256>>>(
        ghs, uhs, a1, ghr, uhr, a2, T*I_DIM/8);
    /* 12. shared down -> out (write) */
    mma_gemm_kernel<<<dim3(H/128, T/128, 1), 256, GSMEM>>>(a1, (const float4*)ws_down, out, 0, 0, H, I_DIM, 0, 0);
    /* 13. routed down -> out (accumulate, grouped, A=h2) */
    mma_gemm_kernel<<<dim3(H/128, T/128, E), 256, GSMEM>>>(a2, (const float4*)we_down, out, 0, 0, H, I_DIM, 1, 1);
}